// round 10
// baseline (speedup 1.0000x reference)
#include <cuda_runtime.h>
#include <math.h>

#define BATCH 4
#define T_SEQ 2048
#define TOK (BATCH*T_SEQ)          // 8192
#define DIMC 512
#define HEADS 8
#define DH 64
#define FRAMES 32

// ---------------- scratch (device globals: allocation-free rule) -------------
static __device__ float g_xn[TOK*DIMC];        // normalized x, tf32-rounded
static __device__ float g_q [TOK*DIMC];        // [B][H][T][64], tf32, pre-scaled 1/8
static __device__ float g_k [TOK*DIMC];        // [B][H][T][64], tf32
static __device__ float g_v [TOK*DIMC];        // [B][H][T][64], tf32
static __device__ float g_vt[TOK*DIMC];        // [B][H][64][T], tf32 (transposed V)
static __device__ float g_att[TOK*DIMC];       // attention out [B][T][H*64], tf32
static __device__ float g_wqkv_t[3*DIMC*DIMC]; // [1536][512] transposed, tf32
static __device__ float g_wout_t[DIMC*DIMC];   // [512][512]  transposed, tf32

// ---------------- tf32 / cp.async helpers ------------------------------------
__device__ __forceinline__ unsigned f2tf(float x) {
    unsigned r; asm("cvt.rna.tf32.f32 %0, %1;" : "=r"(r) : "f"(x)); return r;
}
__device__ __forceinline__ float f2tff(float x) {
    return __uint_as_float(f2tf(x));
}
__device__ __forceinline__ unsigned fu(float x) { return __float_as_uint(x); }

__device__ __forceinline__ void cpa16(void* dst_smem, const void* src_gmem) {
    unsigned d = (unsigned)__cvta_generic_to_shared(dst_smem);
    asm volatile("cp.async.cg.shared.global [%0], [%1], 16;" :: "r"(d), "l"(src_gmem));
}
__device__ __forceinline__ void cpa_commit() {
    asm volatile("cp.async.commit_group;");
}
__device__ __forceinline__ void cpa_wait0() {
    asm volatile("cp.async.wait_group 0;");
}

// k-relabel convention: mma slot (t4, t4+4) <- logical k cols (2t4, 2t4+1).
__device__ __forceinline__ void mma8(float* c, unsigned a0, unsigned a1,
                                     unsigned a2, unsigned a3,
                                     unsigned b0, unsigned b1) {
    asm volatile(
        "mma.sync.aligned.m16n8k8.row.col.f32.tf32.tf32.f32 "
        "{%0,%1,%2,%3},{%4,%5,%6,%7},{%8,%9},{%0,%1,%2,%3};\n"
        : "+f"(c[0]), "+f"(c[1]), "+f"(c[2]), "+f"(c[3])
        : "r"(a0), "r"(a1), "r"(a2), "r"(a3), "r"(b0), "r"(b1));
}

// ---------------- 0) transpose + tf32-convert weights ------------------------
__global__ __launch_bounds__(256) void tr_cvt(
    const float* __restrict__ src, float* __restrict__ dst, int R, int C)
{
    __shared__ float t[32][33];
    int c0 = blockIdx.x * 32, r0 = blockIdx.y * 32;
    int tx = threadIdx.x, ty = threadIdx.y;       // 32 x 8
#pragma unroll
    for (int j = 0; j < 4; j++)
        t[ty + j*8][tx] = src[(size_t)(r0 + ty + j*8) * C + c0 + tx];
    __syncthreads();
#pragma unroll
    for (int j = 0; j < 4; j++)
        dst[(size_t)(c0 + ty + j*8) * R + r0 + tx] = f2tff(t[tx][ty + j*8]);
}

// ---------------- 0b) V transpose per (b,h): [T][64] -> [64][T] --------------
__global__ __launch_bounds__(256) void v_tr(void)
{
    __shared__ float t[32][33];
    int bh = blockIdx.z;
    const float* src = g_v  + (size_t)bh * T_SEQ * DH;
    float*       dst = g_vt + (size_t)bh * T_SEQ * DH;
    int t0 = blockIdx.x * 32, d0 = blockIdx.y * 32;
    int tx = threadIdx.x, ty = threadIdx.y;       // 32 x 8
#pragma unroll
    for (int j = 0; j < 4; j++)
        t[ty + j*8][tx] = src[(size_t)(t0 + ty + j*8) * DH + d0 + tx];
    __syncthreads();
#pragma unroll
    for (int j = 0; j < 4; j++)
        dst[(size_t)(d0 + ty + j*8) * T_SEQ + t0 + tx] = t[tx][ty + j*8];
}

// ---------------- 1) LayerNorm: one warp per token, tf32 output --------------
__global__ __launch_bounds__(256) void ln_kernel(
    const float* __restrict__ x, const float* __restrict__ gam,
    const float* __restrict__ bet)
{
    int warp = threadIdx.x >> 5, lane = threadIdx.x & 31;
    int tok  = blockIdx.x * 8 + warp;
    const float* xr = x + (size_t)tok * DIMC;
    float4 v[4]; float s = 0.f, ss = 0.f;
#pragma unroll
    for (int i = 0; i < 4; i++) {
        v[i] = *(const float4*)(xr + i * 128 + lane * 4);
        s  += v[i].x + v[i].y + v[i].z + v[i].w;
        ss += v[i].x*v[i].x + v[i].y*v[i].y + v[i].z*v[i].z + v[i].w*v[i].w;
    }
#pragma unroll
    for (int o = 16; o > 0; o >>= 1) {
        s  += __shfl_xor_sync(0xffffffffu, s, o);
        ss += __shfl_xor_sync(0xffffffffu, ss, o);
    }
    float mean = s * (1.f/512.f);
    float var  = ss * (1.f/512.f) - mean*mean;
    float rstd = rsqrtf(var + 1e-5f);
    float* orow = g_xn + (size_t)tok * DIMC;
#pragma unroll
    for (int i = 0; i < 4; i++) {
        int col = i * 128 + lane * 4;
        float4 g4 = *(const float4*)(gam + col);
        float4 b4 = *(const float4*)(bet + col);
        float4 r;
        r.x = f2tff((v[i].x - mean) * rstd * g4.x + b4.x);
        r.y = f2tff((v[i].y - mean) * rstd * g4.y + b4.y);
        r.z = f2tff((v[i].z - mean) * rstd * g4.z + b4.z);
        r.w = f2tff((v[i].w - mean) * rstd * g4.w + b4.w);
        *(float4*)(orow + col) = r;
    }
}

#define GS_STR 40   // (40*g + 2*t4) % 32 = 8g+2t4 -> conflict-free LDS.64
#define GEMM_SMEM (2 * 2 * 128 * GS_STR * 4)   // 2 stages x (As+Bs)

// ---------------- 2+4) GEMM: 128x128 block, cp.async double-buffered ---------
template <int WHICH>   // 0 = qkv (epilogue scatter q/k/v), 1 = out (bias+store)
__global__ __launch_bounds__(256) void gemm128(
    const float* __restrict__ Ag, const float* __restrict__ Bt,
    const float* __restrict__ bias, float* __restrict__ outp)
{
    extern __shared__ float smg[];
    float (*As)[128][GS_STR] = (float (*)[128][GS_STR])smg;
    float (*Bs)[128][GS_STR] = (float (*)[128][GS_STR])(smg + 2 * 128 * GS_STR);
    const int K = DIMC;
    int tid = threadIdx.x, warp = tid >> 5, lane = tid & 31;
    int g = lane >> 2, t4 = lane & 3;
    int wm = warp >> 2, wn = warp & 3;            // 2 x 4 warps
    int row0 = blockIdx.y * 128, col0 = blockIdx.x * 128;
    float c[4][4][4] = {};

    int lr = tid >> 3, lc = (tid & 7) * 4;

#pragma unroll
    for (int t = 0; t < 4; t++) {
        int r = lr + t * 32;
        cpa16(&As[0][r][lc], Ag + (size_t)(row0 + r) * K + lc);
        cpa16(&Bs[0][r][lc], Bt + (size_t)(col0 + r) * K + lc);
    }
    cpa_commit();

    int buf = 0;
    for (int it = 0; it < 16; it++) {
        cpa_wait0();
        __syncthreads();
        if (it + 1 < 16) {
            int k0 = (it + 1) * 32;
#pragma unroll
            for (int t = 0; t < 4; t++) {
                int r = lr + t * 32;
                cpa16(&As[buf ^ 1][r][lc], Ag + (size_t)(row0 + r) * K + k0 + lc);
                cpa16(&Bs[buf ^ 1][r][lc], Bt + (size_t)(col0 + r) * K + k0 + lc);
            }
            cpa_commit();
        }
#pragma unroll
        for (int ks = 0; ks < 4; ks++) {
            int kb = ks * 8 + 2 * t4;
            float2 a01[4], a23[4], b[4];
#pragma unroll
            for (int mi = 0; mi < 4; mi++) {
                int rb = wm * 64 + mi * 16;
                a01[mi] = *(const float2*)&As[buf][rb + g    ][kb];
                a23[mi] = *(const float2*)&As[buf][rb + g + 8][kb];
            }
#pragma unroll
            for (int ni = 0; ni < 4; ni++)
                b[ni] = *(const float2*)&Bs[buf][wn * 32 + ni * 8 + g][kb];
#pragma unroll
            for (int mi = 0; mi < 4; mi++)
#pragma unroll
                for (int ni = 0; ni < 4; ni++)
                    mma8(c[mi][ni], fu(a01[mi].x), fu(a23[mi].x),
                         fu(a01[mi].y), fu(a23[mi].y), fu(b[ni].x), fu(b[ni].y));
        }
        buf ^= 1;
    }

#pragma unroll
    for (int mi = 0; mi < 4; mi++) {
        int r0 = row0 + wm * 64 + mi * 16 + g;
        int r1 = r0 + 8;
        if (WHICH == 0) {
            int bb = r0 >> 11;
            int t0i = r0 & 2047, t1i = r1 & 2047;
#pragma unroll
            for (int ni = 0; ni < 4; ni++) {
                int col = col0 + wn * 32 + ni * 8 + 2 * t4;
                int which = col >> 9;
                int hh = (col >> 6) & 7;
                float* dst = (which == 0) ? g_q : ((which == 1) ? g_k : g_v);
                float sc = (which == 0) ? 0.125f : 1.0f;
                size_t base = (((size_t)bb * HEADS + hh) * T_SEQ) * DH + (col & 63);
                size_t i0 = base + (size_t)t0i * DH;
                size_t i1 = base + (size_t)t1i * DH;
                dst[i0]     = f2tff(c[mi][ni][0] * sc);
                dst[i0 + 1] = f2tff(c[mi][ni][1] * sc);
                dst[i1]     = f2tff(c[mi][ni][2] * sc);
                dst[i1 + 1] = f2tff(c[mi][ni][3] * sc);
            }
        } else {
#pragma unroll
            for (int ni = 0; ni < 4; ni++) {
                int col = col0 + wn * 32 + ni * 8 + 2 * t4;
                float bz0 = bias[col], bz1 = bias[col + 1];
                outp[(size_t)r0 * DIMC + col]     = c[mi][ni][0] + bz0;
                outp[(size_t)r0 * DIMC + col + 1] = c[mi][ni][1] + bz1;
                outp[(size_t)r1 * DIMC + col]     = c[mi][ni][2] + bz0;
                outp[(size_t)r1 * DIMC + col + 1] = c[mi][ni][3] + bz1;
            }
        }
    }
}

// ---------------- 3) frame-PAIRED flash attention ----------------------------
// One 256-thread CTA handles frames (2j, 2j+1): warps 0-3 -> frame 2j,
// warps 4-7 -> frame 2j+1, sharing the K/V cp.async pipeline.
// Stage layout (per stage, 128 rows x KS_STR): rows 0-63 = K tile [key][dh],
// rows 64-127 = V^T tile [dh][key].
#define KS_STR 72
#define A_STAGE (128 * KS_STR)             // floats per stage
#define ATTN_SMEM (2 * A_STAGE * 4)

__global__ __launch_bounds__(256) void attn_kernel(void)
{
    extern __shared__ float sm[];

    int jp = 15 - blockIdx.x;           // heavy pairs first
    int f0 = 2 * jp, f1 = f0 + 1;
    int h = blockIdx.y, b = blockIdx.z;
    int tid = threadIdx.x, warp = tid >> 5, lane = tid & 31;
    int wg = warp >> 2, wi = warp & 3;
    int g = lane >> 2, t4 = lane & 3;
    int f = f0 + wg;                    // this warp's frame
    size_t bh = ((size_t)b * HEADS + h) * T_SEQ * DH;
    const float* qb  = g_q  + bh;
    const float* kb  = g_k  + bh;
    const float* vtb = g_vt + bh;       // [64 dh][T]
    int t0q = f0 * 64;                  // CTA's first query row (128 contiguous)
    int wrow = wg * 64 + wi * 16;       // local query row 0..127

    // stage all 128 Q rows into stage-0 smem, pull fragments to registers
    int lr = tid >> 4, lc = (tid & 15) * 4;
#pragma unroll
    for (int i = 0; i < 8; i++) {
        int r = lr + i * 16;
        *(float4*)&sm[r * KS_STR + lc] =
            *(const float4*)(qb + (size_t)(t0q + r) * DH + lc);
    }
    __syncthreads();
    float2 qa[8][2];
#pragma unroll
    for (int ks = 0; ks < 8; ks++) {
        int kc = ks * 8 + 2 * t4;
        qa[ks][0] = *(const float2*)&sm[(wrow + g    ) * KS_STR + kc];
        qa[ks][1] = *(const float2*)&sm[(wrow + g + 8) * KS_STR + kc];
    }
    __syncthreads();

    // prologue: async-load K/V tile 0 into stage 0
#pragma unroll
    for (int i = 0; i < 8; i++) {
        int idx = tid + i * 256;
        int r = idx >> 4, c4 = (idx & 15) * 4;
        const float* src = (r < 64)
            ? (kb  + (size_t)r * DH + c4)
            : (vtb + (size_t)(r - 64) * T_SEQ + c4);
        cpa16(&sm[r * KS_STR + c4], src);
    }
    cpa_commit();

    float m0 = -1e30f, m1 = -1e30f, l0 = 0.f, l1 = 0.f;
    float o[8][4] = {};
    int buf = 0;

    for (int kt = 0; kt <= f1; kt++) {
        cpa_wait0();
        __syncthreads();
        float* Ks  = sm + buf * A_STAGE;
        float* Vst = Ks + 64 * KS_STR;
        if (kt + 1 <= f1) {
            int nt0 = (kt + 1) * 64;
            float* Kn = sm + (buf ^ 1) * A_STAGE;
#pragma unroll
            for (int i = 0; i < 8; i++) {
                int idx = tid + i * 256;
                int r = idx >> 4, c4 = (idx & 15) * 4;
                const float* src = (r < 64)
                    ? (kb  + (size_t)(nt0 + r) * DH + c4)
                    : (vtb + (size_t)(r - 64) * T_SEQ + nt0 + c4);
                cpa16(&Kn[r * KS_STR + c4], src);
            }
            cpa_commit();
        }

        if (kt <= f) {
            // S = Q K^T : 16 q rows x 64 keys per warp
            float s[8][4] = {};
#pragma unroll
            for (int ks = 0; ks < 8; ks++) {
                int kc = ks * 8 + 2 * t4;
#pragma unroll
                for (int n = 0; n < 8; n++) {
                    float2 b2 = *(const float2*)&Ks[(n * 8 + g) * KS_STR + kc];
                    mma8(s[n], fu(qa[ks][0].x), fu(qa[ks][1].x),
                         fu(qa[ks][0].y), fu(qa[ks][1].y), fu(b2.x), fu(b2.y));
                }
            }

            // online softmax (rows g, g+8 of this warp's strip)
            float mx0 = -1e30f, mx1 = -1e30f;
#pragma unroll
            for (int n = 0; n < 8; n++) {
                mx0 = fmaxf(mx0, fmaxf(s[n][0], s[n][1]));
                mx1 = fmaxf(mx1, fmaxf(s[n][2], s[n][3]));
            }
            mx0 = fmaxf(mx0, __shfl_xor_sync(0xffffffffu, mx0, 1));
            mx0 = fmaxf(mx0, __shfl_xor_sync(0xffffffffu, mx0, 2));
            mx1 = fmaxf(mx1, __shfl_xor_sync(0xffffffffu, mx1, 1));
            mx1 = fmaxf(mx1, __shfl_xor_sync(0xffffffffu, mx1, 2));
            float mn0 = fmaxf(m0, mx0), mn1 = fmaxf(m1, mx1);
            float al0 = __expf(m0 - mn0), al1 = __expf(m1 - mn1);
            float sum0 = 0.f, sum1 = 0.f;
#pragma unroll
            for (int n = 0; n < 8; n++) {
                s[n][0] = __expf(s[n][0] - mn0);
                s[n][1] = __expf(s[n][1] - mn0);
                s[n][2] = __expf(s[n][2] - mn1);
                s[n][3] = __expf(s[n][3] - mn1);
                sum0 += s[n][0] + s[n][1];
                sum1 += s[n][2] + s[n][3];
            }
            sum0 += __shfl_xor_sync(0xffffffffu, sum0, 1);
            sum0 += __shfl_xor_sync(0xffffffffu, sum0, 2);
            sum1 += __shfl_xor_sync(0xffffffffu, sum1, 1);
            sum1 += __shfl_xor_sync(0xffffffffu, sum1, 2);
            l0 = l0 * al0 + sum0;  l1 = l1 * al1 + sum1;
            m0 = mn0;  m1 = mn1;
#pragma unroll
            for (int n = 0; n < 8; n++) {
                o[n][0] *= al0; o[n][1] *= al0;
                o[n][2] *= al1; o[n][3] *= al1;
                s[n][0] = f2tff(s[n][0]);
                s[n][1] = f2tff(s[n][1]);
                s[n][2] = f2tff(s[n][2]);
                s[n][3] = f2tff(s[n][3]);
            }

            // O += P * V : C-frag s[ks] IS the A-frag for key-group ks.
#pragma unroll
            for (int ks = 0; ks < 8; ks++) {
                int kc = ks * 8 + 2 * t4;
#pragma unroll
                for (int n = 0; n < 8; n++) {
                    float2 b2 = *(const float2*)&Vst[(n * 8 + g) * KS_STR + kc];
                    mma8(o[n], fu(s[ks][0]), fu(s[ks][2]),
                         fu(s[ks][1]), fu(s[ks][3]), fu(b2.x), fu(b2.y));
                }
            }
        }
        buf ^= 1;
    }

    float inv0 = 1.f / l0, inv1 = 1.f / l1;
    int q0 = t0q + wrow + g, q1 = q0 + 8;
    float* out0 = g_att + ((size_t)b * T_SEQ + q0) * DIMC + h * DH;
    float* out1 = g_att + ((size_t)b * T_SEQ + q1) * DIMC + h * DH;
#pragma unroll
    for (int n = 0; n < 8; n++) {
        int cc = n * 8 + t4 * 2;
        out0[cc]     = f2tff(o[n][0] * inv0);
        out0[cc + 1] = f2tff(o[n][1] * inv0);
        out1[cc]     = f2tff(o[n][2] * inv1);
        out1[cc + 1] = f2tff(o[n][3] * inv1);
    }
}

// ---------------- launch -----------------------------------------------------
extern "C" void kernel_launch(void* const* d_in, const int* in_sizes, int n_in,
                              void* d_out, int out_size)
{
    (void)in_sizes; (void)n_in; (void)out_size;
    const float* x     = (const float*)d_in[0];
    const float* ln_g  = (const float*)d_in[1];
    const float* ln_b  = (const float*)d_in[2];
    const float* w_qkv = (const float*)d_in[3];
    const float* w_out = (const float*)d_in[4];
    const float* b_out = (const float*)d_in[5];
    float* out = (float*)d_out;

    cudaFuncSetAttribute(attn_kernel,
                         cudaFuncAttributeMaxDynamicSharedMemorySize, ATTN_SMEM);
    cudaFuncSetAttribute(gemm128<0>,
                         cudaFuncAttributeMaxDynamicSharedMemorySize, GEMM_SMEM);
    cudaFuncSetAttribute(gemm128<1>,
                         cudaFuncAttributeMaxDynamicSharedMemorySize, GEMM_SMEM);

    float *wqkv_t, *wout_t, *xn_p, *att_p;
    cudaGetSymbolAddress((void**)&wqkv_t, g_wqkv_t);
    cudaGetSymbolAddress((void**)&wout_t, g_wout_t);
    cudaGetSymbolAddress((void**)&xn_p,   g_xn);
    cudaGetSymbolAddress((void**)&att_p,  g_att);

    tr_cvt<<<dim3(3*DIMC/32, DIMC/32), dim3(32, 8)>>>(w_qkv, wqkv_t, DIMC, 3*DIMC);
    tr_cvt<<<dim3(DIMC/32, DIMC/32), dim3(32, 8)>>>(w_out, wout_t, DIMC, DIMC);
    ln_kernel<<<TOK / 8, 256>>>(x, ln_g, ln_b);
    gemm128<0><<<dim3(3 * DIMC / 128, TOK / 128), 256, GEMM_SMEM>>>(xn_p, wqkv_t, nullptr, nullptr);
    v_tr<<<dim3(T_SEQ / 32, DH / 32, BATCH * HEADS), dim3(32, 8)>>>();
    attn_kernel<<<dim3(FRAMES / 2, HEADS, BATCH), 256, ATTN_SMEM>>>();
    gemm128<1><<<dim3(DIMC / 128, TOK / 128), 256, GEMM_SMEM>>>(att_p, wout_t, b_out, out);
}

// round 11
// speedup vs baseline: 1.1213x; 1.1213x over previous
#include <cuda_runtime.h>
#include <math.h>

#define BATCH 4
#define T_SEQ 2048
#define TOK (BATCH*T_SEQ)          // 8192
#define DIMC 512
#define HEADS 8
#define DH 64
#define FRAMES 32

// ---------------- scratch (device globals: allocation-free rule) -------------
static __device__ float g_xn[TOK*DIMC];        // normalized x, tf32-rounded
static __device__ float g_q [TOK*DIMC];        // [B][H][T][64], tf32, pre-scaled log2e/8
static __device__ float g_k [TOK*DIMC];        // [B][H][T][64], tf32
static __device__ float g_v [TOK*DIMC];        // [B][H][T][64], tf32
static __device__ float g_vt[TOK*DIMC];        // [B][H][64][T], tf32 (transposed V)
static __device__ float g_att[TOK*DIMC];       // attention out [B][T][H*64], tf32
static __device__ float g_wqkv_t[3*DIMC*DIMC]; // [1536][512] transposed, tf32
static __device__ float g_wout_t[DIMC*DIMC];   // [512][512]  transposed, tf32

// ---------------- tf32 / cp.async helpers ------------------------------------
__device__ __forceinline__ unsigned f2tf(float x) {
    unsigned r; asm("cvt.rna.tf32.f32 %0, %1;" : "=r"(r) : "f"(x)); return r;
}
__device__ __forceinline__ float f2tff(float x) {
    return __uint_as_float(f2tf(x));
}
__device__ __forceinline__ unsigned fu(float x) { return __float_as_uint(x); }
__device__ __forceinline__ float ex2(float x) {   // bare MUFU.EX2 (log2 domain)
    float r; asm("ex2.approx.f32 %0, %1;" : "=f"(r) : "f"(x)); return r;
}

__device__ __forceinline__ void cpa16(void* dst_smem, const void* src_gmem) {
    unsigned d = (unsigned)__cvta_generic_to_shared(dst_smem);
    asm volatile("cp.async.cg.shared.global [%0], [%1], 16;" :: "r"(d), "l"(src_gmem));
}
__device__ __forceinline__ void cpa_commit() {
    asm volatile("cp.async.commit_group;");
}
__device__ __forceinline__ void cpa_wait0() {
    asm volatile("cp.async.wait_group 0;");
}

// k-relabel convention: mma slot (t4, t4+4) <- logical k cols (2t4, 2t4+1).
__device__ __forceinline__ void mma8(float* c, unsigned a0, unsigned a1,
                                     unsigned a2, unsigned a3,
                                     unsigned b0, unsigned b1) {
    asm volatile(
        "mma.sync.aligned.m16n8k8.row.col.f32.tf32.tf32.f32 "
        "{%0,%1,%2,%3},{%4,%5,%6,%7},{%8,%9},{%0,%1,%2,%3};\n"
        : "+f"(c[0]), "+f"(c[1]), "+f"(c[2]), "+f"(c[3])
        : "r"(a0), "r"(a1), "r"(a2), "r"(a3), "r"(b0), "r"(b1));
}

// ---------------- 0) transpose + tf32-convert weights ------------------------
__global__ __launch_bounds__(256) void tr_cvt(
    const float* __restrict__ src, float* __restrict__ dst, int R, int C)
{
    __shared__ float t[32][33];
    int c0 = blockIdx.x * 32, r0 = blockIdx.y * 32;
    int tx = threadIdx.x, ty = threadIdx.y;       // 32 x 8
#pragma unroll
    for (int j = 0; j < 4; j++)
        t[ty + j*8][tx] = src[(size_t)(r0 + ty + j*8) * C + c0 + tx];
    __syncthreads();
#pragma unroll
    for (int j = 0; j < 4; j++)
        dst[(size_t)(c0 + ty + j*8) * R + r0 + tx] = f2tff(t[tx][ty + j*8]);
}

// ---------------- 0b) V transpose per (b,h): [T][64] -> [64][T] --------------
__global__ __launch_bounds__(256) void v_tr(void)
{
    __shared__ float t[32][33];
    int bh = blockIdx.z;
    const float* src = g_v  + (size_t)bh * T_SEQ * DH;
    float*       dst = g_vt + (size_t)bh * T_SEQ * DH;
    int t0 = blockIdx.x * 32, d0 = blockIdx.y * 32;
    int tx = threadIdx.x, ty = threadIdx.y;       // 32 x 8
#pragma unroll
    for (int j = 0; j < 4; j++)
        t[ty + j*8][tx] = src[(size_t)(t0 + ty + j*8) * DH + d0 + tx];
    __syncthreads();
#pragma unroll
    for (int j = 0; j < 4; j++)
        dst[(size_t)(d0 + ty + j*8) * T_SEQ + t0 + tx] = t[tx][ty + j*8];
}

// ---------------- 1) LayerNorm: one warp per token, tf32 output --------------
__global__ __launch_bounds__(256) void ln_kernel(
    const float* __restrict__ x, const float* __restrict__ gam,
    const float* __restrict__ bet)
{
    int warp = threadIdx.x >> 5, lane = threadIdx.x & 31;
    int tok  = blockIdx.x * 8 + warp;
    const float* xr = x + (size_t)tok * DIMC;
    float4 v[4]; float s = 0.f, ss = 0.f;
#pragma unroll
    for (int i = 0; i < 4; i++) {
        v[i] = *(const float4*)(xr + i * 128 + lane * 4);
        s  += v[i].x + v[i].y + v[i].z + v[i].w;
        ss += v[i].x*v[i].x + v[i].y*v[i].y + v[i].z*v[i].z + v[i].w*v[i].w;
    }
#pragma unroll
    for (int o = 16; o > 0; o >>= 1) {
        s  += __shfl_xor_sync(0xffffffffu, s, o);
        ss += __shfl_xor_sync(0xffffffffu, ss, o);
    }
    float mean = s * (1.f/512.f);
    float var  = ss * (1.f/512.f) - mean*mean;
    float rstd = rsqrtf(var + 1e-5f);
    float* orow = g_xn + (size_t)tok * DIMC;
#pragma unroll
    for (int i = 0; i < 4; i++) {
        int col = i * 128 + lane * 4;
        float4 g4 = *(const float4*)(gam + col);
        float4 b4 = *(const float4*)(bet + col);
        float4 r;
        r.x = f2tff((v[i].x - mean) * rstd * g4.x + b4.x);
        r.y = f2tff((v[i].y - mean) * rstd * g4.y + b4.y);
        r.z = f2tff((v[i].z - mean) * rstd * g4.z + b4.z);
        r.w = f2tff((v[i].w - mean) * rstd * g4.w + b4.w);
        *(float4*)(orow + col) = r;
    }
}

#define GS_STR 40   // (40*g + 2*t4) % 32 = 8g+2t4 -> conflict-free LDS.64
#define GEMM_SMEM (2 * 2 * 128 * GS_STR * 4)   // 2 stages x (As+Bs)

// ---------------- 2+4) GEMM: 128x128 block, cp.async double-buffered ---------
template <int WHICH>   // 0 = qkv (epilogue scatter q/k/v), 1 = out (bias+store)
__global__ __launch_bounds__(256) void gemm128(
    const float* __restrict__ Ag, const float* __restrict__ Bt,
    const float* __restrict__ bias, float* __restrict__ outp)
{
    extern __shared__ float smg[];
    float (*As)[128][GS_STR] = (float (*)[128][GS_STR])smg;
    float (*Bs)[128][GS_STR] = (float (*)[128][GS_STR])(smg + 2 * 128 * GS_STR);
    const int K = DIMC;
    int tid = threadIdx.x, warp = tid >> 5, lane = tid & 31;
    int g = lane >> 2, t4 = lane & 3;
    int wm = warp >> 2, wn = warp & 3;            // 2 x 4 warps
    int row0 = blockIdx.y * 128, col0 = blockIdx.x * 128;
    float c[4][4][4] = {};

    int lr = tid >> 3, lc = (tid & 7) * 4;

#pragma unroll
    for (int t = 0; t < 4; t++) {
        int r = lr + t * 32;
        cpa16(&As[0][r][lc], Ag + (size_t)(row0 + r) * K + lc);
        cpa16(&Bs[0][r][lc], Bt + (size_t)(col0 + r) * K + lc);
    }
    cpa_commit();

    int buf = 0;
    for (int it = 0; it < 16; it++) {
        cpa_wait0();
        __syncthreads();
        if (it + 1 < 16) {
            int k0 = (it + 1) * 32;
#pragma unroll
            for (int t = 0; t < 4; t++) {
                int r = lr + t * 32;
                cpa16(&As[buf ^ 1][r][lc], Ag + (size_t)(row0 + r) * K + k0 + lc);
                cpa16(&Bs[buf ^ 1][r][lc], Bt + (size_t)(col0 + r) * K + k0 + lc);
            }
            cpa_commit();
        }
#pragma unroll
        for (int ks = 0; ks < 4; ks++) {
            int kb = ks * 8 + 2 * t4;
            float2 a01[4], a23[4], b[4];
#pragma unroll
            for (int mi = 0; mi < 4; mi++) {
                int rb = wm * 64 + mi * 16;
                a01[mi] = *(const float2*)&As[buf][rb + g    ][kb];
                a23[mi] = *(const float2*)&As[buf][rb + g + 8][kb];
            }
#pragma unroll
            for (int ni = 0; ni < 4; ni++)
                b[ni] = *(const float2*)&Bs[buf][wn * 32 + ni * 8 + g][kb];
#pragma unroll
            for (int mi = 0; mi < 4; mi++)
#pragma unroll
                for (int ni = 0; ni < 4; ni++)
                    mma8(c[mi][ni], fu(a01[mi].x), fu(a23[mi].x),
                         fu(a01[mi].y), fu(a23[mi].y), fu(b[ni].x), fu(b[ni].y));
        }
        buf ^= 1;
    }

#pragma unroll
    for (int mi = 0; mi < 4; mi++) {
        int r0 = row0 + wm * 64 + mi * 16 + g;
        int r1 = r0 + 8;
        if (WHICH == 0) {
            int bb = r0 >> 11;
            int t0i = r0 & 2047, t1i = r1 & 2047;
#pragma unroll
            for (int ni = 0; ni < 4; ni++) {
                int col = col0 + wn * 32 + ni * 8 + 2 * t4;
                int which = col >> 9;
                int hh = (col >> 6) & 7;
                float* dst = (which == 0) ? g_q : ((which == 1) ? g_k : g_v);
                // q: fold 1/sqrt(dh) AND log2(e) so softmax is pure ex2
                float sc = (which == 0) ? 0.125f * 1.4426950408889634f : 1.0f;
                size_t base = (((size_t)bb * HEADS + hh) * T_SEQ) * DH + (col & 63);
                size_t i0 = base + (size_t)t0i * DH;
                size_t i1 = base + (size_t)t1i * DH;
                dst[i0]     = f2tff(c[mi][ni][0] * sc);
                dst[i0 + 1] = f2tff(c[mi][ni][1] * sc);
                dst[i1]     = f2tff(c[mi][ni][2] * sc);
                dst[i1 + 1] = f2tff(c[mi][ni][3] * sc);
            }
        } else {
#pragma unroll
            for (int ni = 0; ni < 4; ni++) {
                int col = col0 + wn * 32 + ni * 8 + 2 * t4;
                float bz0 = bias[col], bz1 = bias[col + 1];
                outp[(size_t)r0 * DIMC + col]     = c[mi][ni][0] + bz0;
                outp[(size_t)r0 * DIMC + col + 1] = c[mi][ni][1] + bz1;
                outp[(size_t)r1 * DIMC + col]     = c[mi][ni][2] + bz0;
                outp[(size_t)r1 * DIMC + col + 1] = c[mi][ni][3] + bz1;
            }
        }
    }
}

// ---------------- 3) frame-causal flash attention (R7 structure) --------------
// 2-stage cp.async pipeline; P in registers; V transposed in smem.
// Scores are in the log2 domain (q pre-scaled by log2e/8) -> softmax uses ex2.
#define KS_STR 72
#define ATTN_SMEM (2 * (64*KS_STR + 64*KS_STR) * 4)

__global__ __launch_bounds__(128) void attn_kernel(void)
{
    extern __shared__ float sm[];
    const int STAGE = 64 * KS_STR * 2;
    float* Ks0  = sm;
    float* Vs0  = sm + 64 * KS_STR;

    int f = 31 - blockIdx.x;            // heavy frames first
    int h = blockIdx.y, b = blockIdx.z;
    int tid = threadIdx.x, warp = tid >> 5, lane = tid & 31;
    int g = lane >> 2, t4 = lane & 3;
    size_t bh = ((size_t)b * HEADS + h) * T_SEQ * DH;
    const float* qb  = g_q  + bh;
    const float* kb  = g_k  + bh;
    const float* vtb = g_vt + bh;       // [64 dh][T]
    int t0 = f * 64;
    int wrow = warp * 16;
    int lr = tid >> 4, lc = (tid & 15) * 4;

    // stage Q through Ks0, pull this warp's a-fragments into registers
#pragma unroll
    for (int i = 0; i < 8; i++) {
        int r = lr + i * 8;
        *(float4*)&Ks0[r * KS_STR + lc] = *(const float4*)(qb + (size_t)(t0 + r) * DH + lc);
    }
    __syncthreads();
    float2 qa[8][2];
#pragma unroll
    for (int ks = 0; ks < 8; ks++) {
        int kc = ks * 8 + 2 * t4;
        qa[ks][0] = *(const float2*)&Ks0[(wrow + g    ) * KS_STR + kc];
        qa[ks][1] = *(const float2*)&Ks0[(wrow + g + 8) * KS_STR + kc];
    }
    __syncthreads();

    // prologue: async-load K/V tile 0 into stage 0
#pragma unroll
    for (int i = 0; i < 8; i++) {
        int r = lr + i * 8;
        cpa16(&Ks0[r * KS_STR + lc], kb  + (size_t)r * DH + lc);
        cpa16(&Vs0[r * KS_STR + lc], vtb + (size_t)r * T_SEQ + lc);
    }
    cpa_commit();

    float m0 = -1e30f, m1 = -1e30f, l0 = 0.f, l1 = 0.f;
    float o[8][4] = {};
    int buf = 0;

    for (int kt = 0; kt <= f; kt++) {
        cpa_wait0();
        __syncthreads();
        float* Ks  = sm + buf * STAGE;
        float* Vst = Ks + 64 * KS_STR;
        if (kt + 1 <= f) {
            int nt0 = (kt + 1) * 64;
            float* Kn = sm + (buf ^ 1) * STAGE;
            float* Vn = Kn + 64 * KS_STR;
#pragma unroll
            for (int i = 0; i < 8; i++) {
                int r = lr + i * 8;
                cpa16(&Kn[r * KS_STR + lc], kb  + (size_t)(nt0 + r) * DH + lc);
                cpa16(&Vn[r * KS_STR + lc], vtb + (size_t)r * T_SEQ + nt0 + lc);
            }
            cpa_commit();
        }

        // S' = (Q*log2e/8) K^T : log2-domain scores
        float s[8][4] = {};
#pragma unroll
        for (int ks = 0; ks < 8; ks++) {
            int kc = ks * 8 + 2 * t4;
#pragma unroll
            for (int n = 0; n < 8; n++) {
                float2 b2 = *(const float2*)&Ks[(n * 8 + g) * KS_STR + kc];
                mma8(s[n], fu(qa[ks][0].x), fu(qa[ks][1].x),
                     fu(qa[ks][0].y), fu(qa[ks][1].y), fu(b2.x), fu(b2.y));
            }
        }

        // online softmax in log2 domain (rows g, g+8 of this warp's strip)
        float mx0 = -1e30f, mx1 = -1e30f;
#pragma unroll
        for (int n = 0; n < 8; n++) {
            mx0 = fmaxf(mx0, fmaxf(s[n][0], s[n][1]));
            mx1 = fmaxf(mx1, fmaxf(s[n][2], s[n][3]));
        }
        mx0 = fmaxf(mx0, __shfl_xor_sync(0xffffffffu, mx0, 1));
        mx0 = fmaxf(mx0, __shfl_xor_sync(0xffffffffu, mx0, 2));
        mx1 = fmaxf(mx1, __shfl_xor_sync(0xffffffffu, mx1, 1));
        mx1 = fmaxf(mx1, __shfl_xor_sync(0xffffffffu, mx1, 2));
        float mn0 = fmaxf(m0, mx0), mn1 = fmaxf(m1, mx1);
        float al0 = ex2(m0 - mn0), al1 = ex2(m1 - mn1);
        float sum0 = 0.f, sum1 = 0.f;
#pragma unroll
        for (int n = 0; n < 8; n++) {
            s[n][0] = ex2(s[n][0] - mn0);
            s[n][1] = ex2(s[n][1] - mn0);
            s[n][2] = ex2(s[n][2] - mn1);
            s[n][3] = ex2(s[n][3] - mn1);
            sum0 += s[n][0] + s[n][1];
            sum1 += s[n][2] + s[n][3];
        }
        sum0 += __shfl_xor_sync(0xffffffffu, sum0, 1);
        sum0 += __shfl_xor_sync(0xffffffffu, sum0, 2);
        sum1 += __shfl_xor_sync(0xffffffffu, sum1, 1);
        sum1 += __shfl_xor_sync(0xffffffffu, sum1, 2);
        l0 = l0 * al0 + sum0;  l1 = l1 * al1 + sum1;
        m0 = mn0;  m1 = mn1;
#pragma unroll
        for (int n = 0; n < 8; n++) {
            o[n][0] *= al0; o[n][1] *= al0;
            o[n][2] *= al1; o[n][3] *= al1;
            s[n][0] = f2tff(s[n][0]);
            s[n][1] = f2tff(s[n][1]);
            s[n][2] = f2tff(s[n][2]);
            s[n][3] = f2tff(s[n][3]);
        }

        // O += P * V : C-frag s[ks] IS the A-frag for key-group ks.
#pragma unroll
        for (int ks = 0; ks < 8; ks++) {
            int kc = ks * 8 + 2 * t4;
#pragma unroll
            for (int n = 0; n < 8; n++) {
                float2 b2 = *(const float2*)&Vst[(n * 8 + g) * KS_STR + kc];
                mma8(o[n], fu(s[ks][0]), fu(s[ks][2]), fu(s[ks][1]), fu(s[ks][3]),
                     fu(b2.x), fu(b2.y));
            }
        }
        buf ^= 1;
    }

    float inv0 = 1.f / l0, inv1 = 1.f / l1;
    int q0 = t0 + wrow + g, q1 = q0 + 8;
    float* out0 = g_att + ((size_t)b * T_SEQ + q0) * DIMC + h * DH;
    float* out1 = g_att + ((size_t)b * T_SEQ + q1) * DIMC + h * DH;
#pragma unroll
    for (int n = 0; n < 8; n++) {
        int cc = n * 8 + t4 * 2;
        out0[cc]     = f2tff(o[n][0] * inv0);
        out0[cc + 1] = f2tff(o[n][1] * inv0);
        out1[cc]     = f2tff(o[n][2] * inv1);
        out1[cc + 1] = f2tff(o[n][3] * inv1);
    }
}

// ---------------- launch -----------------------------------------------------
extern "C" void kernel_launch(void* const* d_in, const int* in_sizes, int n_in,
                              void* d_out, int out_size)
{
    (void)in_sizes; (void)n_in; (void)out_size;
    const float* x     = (const float*)d_in[0];
    const float* ln_g  = (const float*)d_in[1];
    const float* ln_b  = (const float*)d_in[2];
    const float* w_qkv = (const float*)d_in[3];
    const float* w_out = (const float*)d_in[4];
    const float* b_out = (const float*)d_in[5];
    float* out = (float*)d_out;

    cudaFuncSetAttribute(attn_kernel,
                         cudaFuncAttributeMaxDynamicSharedMemorySize, ATTN_SMEM);
    cudaFuncSetAttribute(gemm128<0>,
                         cudaFuncAttributeMaxDynamicSharedMemorySize, GEMM_SMEM);
    cudaFuncSetAttribute(gemm128<1>,
                         cudaFuncAttributeMaxDynamicSharedMemorySize, GEMM_SMEM);

    float *wqkv_t, *wout_t, *xn_p, *att_p;
    cudaGetSymbolAddress((void**)&wqkv_t, g_wqkv_t);
    cudaGetSymbolAddress((void**)&wout_t, g_wout_t);
    cudaGetSymbolAddress((void**)&xn_p,   g_xn);
    cudaGetSymbolAddress((void**)&att_p,  g_att);

    tr_cvt<<<dim3(3*DIMC/32, DIMC/32), dim3(32, 8)>>>(w_qkv, wqkv_t, DIMC, 3*DIMC);
    tr_cvt<<<dim3(DIMC/32, DIMC/32), dim3(32, 8)>>>(w_out, wout_t, DIMC, DIMC);
    ln_kernel<<<TOK / 8, 256>>>(x, ln_g, ln_b);
    gemm128<0><<<dim3(3 * DIMC / 128, TOK / 128), 256, GEMM_SMEM>>>(xn_p, wqkv_t, nullptr, nullptr);
    v_tr<<<dim3(T_SEQ / 32, DH / 32, BATCH * HEADS), dim3(32, 8)>>>();
    attn_kernel<<<dim3(FRAMES, HEADS, BATCH), 128, ATTN_SMEM>>>();
    gemm128<1><<<dim3(DIMC / 128, TOK / 128), 256, GEMM_SMEM>>>(att_p, wout_t, b_out, out);
}